// round 16
// baseline (speedup 1.0000x reference)
#include <cuda_runtime.h>
#include <cuda_bf16.h>

// Problem constants
#define CDIM 512
#define NSEG 640         // S
#define PPP  250         // points per segment
#define NB   32          // BO
#define NERF 147         // 7 + 7*10*2
#define NBLK 296         // persistent grid: 2 blocks/SM on 148 SMs
#define KAUG 152         // 147 nerf + 1 bias + 3 ctr + 1 zero pad

// Scratch (__device__ globals; allocation-free rule)
__device__ float g_ctr  [NSEG*3];
__device__ float g_nerf [NSEG*NERF];
__device__ float g_E32  [NB*CDIM];
__device__ float g_th   [NB*CDIM];    // silu hidden
__device__ float g_TB   [NB*256];     // th @ W2a + ba (== temb@o_w1 + o_b1)
__device__ float g_PWa  [KAUG*256];   // [PFW; peb+pfb; PEW; 0] @ o_w1
__device__ float g_W2a  [CDIM*256];   // tw2 @ o_w1
__device__ float g_ba   [256];        // tb2 @ o_w1 + o_b1
__device__ float g_Y1   [NSEG*256];
__device__ float g_Y2   [NSEG*128];
// BN stats: [0,256) sum1 | [256,512) sumsq1 | [512,640) sum2 | [640,768) sumsq2
__device__ float g_stats[768];

// Flag-based sync: monotonic counters (128B apart), epoch via ticket counter.
__device__ unsigned g_tickets;
__device__ unsigned g_c[7*32];
#define C_A    0   // Y1-side producers (seg prep + PWa)  target/epoch: 160
#define C_E32  1   // E32 rows + stats zero               5
#define C_W2A  2   // W2a tiles + ba items                130
#define C_TH   3   // th tiles                            64
#define C_TB   4   // TB tiles                            32
#define C_Y1   5   // Y1 tiles                            160
#define C_Y2   6   // Y2 tiles                            160

__device__ __forceinline__ void wait_ge(int ci, unsigned tgt)
{
    if (threadIdx.x == 0) {
        while (((volatile unsigned*)g_c)[ci*32] < tgt) __nanosleep(40);
        __threadfence();
    }
    __syncthreads();
}
__device__ __forceinline__ void signal(int ci)
{
    __threadfence();
    __syncthreads();
    if (threadIdx.x == 0) atomicAdd(&g_c[ci*32], 1u);
}

// K=256 half-slice FMA: A in smem [8][512], W global row-stride 256.
__device__ __forceinline__ void kslice512(const float* __restrict__ As,
                                          const float* __restrict__ Wp,
                                          int kbase, float acc[8])
{
    for (int k0 = 0; k0 < 256; k0 += 8) {
        float w[8];
        #pragma unroll
        for (int u = 0; u < 8; u++) w[u] = Wp[(long)(k0+u)*256];
        #pragma unroll
        for (int r = 0; r < 8; r++) {
            const float* e = As + r*CDIM + kbase + k0;
            float4 e0 = *(const float4*)e;
            float4 e1 = *(const float4*)(e+4);
            acc[r] = fmaf(e0.x, w[0], acc[r]);
            acc[r] = fmaf(e0.y, w[1], acc[r]);
            acc[r] = fmaf(e0.z, w[2], acc[r]);
            acc[r] = fmaf(e0.w, w[3], acc[r]);
            acc[r] = fmaf(e1.x, w[4], acc[r]);
            acc[r] = fmaf(e1.y, w[5], acc[r]);
            acc[r] = fmaf(e1.z, w[6], acc[r]);
            acc[r] = fmaf(e1.w, w[7], acc[r]);
        }
    }
}

// 32-row MLP tile: 8r x 32c, 8-way split-K (K=512). W row-stride WS.
template<int WS, bool SILU>
__device__ __forceinline__ void mlp_tile(float* sm, int tid, int lane, int t,
                                         const float* __restrict__ Ein,
                                         const float* __restrict__ W,
                                         const float* __restrict__ B,
                                         float* __restrict__ Out, int outstride)
{
    float* Es = sm;            // [8][512]
    float* ps = sm + 4096;     // [7][8][32]
    int ks = tid >> 5;
    int r0 = (t & 3) * 8;
    int c  = (t >> 2) * 32 + lane;
    for (int idx = tid; idx < 8*128; idx += 256) {
        int r = idx >> 7, q = idx & 127;
        ((float4*)(Es + r*CDIM))[q] = ((const float4*)(Ein + (r0+r)*CDIM))[q];
    }
    __syncthreads();
    int kbase = ks * 64;
    const float* Wp = W + (long)kbase * WS + c;
    float acc[8];
    #pragma unroll
    for (int r = 0; r < 8; r++) acc[r] = 0.f;
    for (int k0 = 0; k0 < 64; k0 += 8) {
        float w[8];
        #pragma unroll
        for (int u = 0; u < 8; u++) w[u] = Wp[(long)(k0+u)*WS];
        #pragma unroll
        for (int r = 0; r < 8; r++) {
            const float* e = Es + r*CDIM + kbase + k0;
            float4 e0 = *(const float4*)e;
            float4 e1 = *(const float4*)(e+4);
            acc[r] = fmaf(e0.x, w[0], acc[r]);
            acc[r] = fmaf(e0.y, w[1], acc[r]);
            acc[r] = fmaf(e0.z, w[2], acc[r]);
            acc[r] = fmaf(e0.w, w[3], acc[r]);
            acc[r] = fmaf(e1.x, w[4], acc[r]);
            acc[r] = fmaf(e1.y, w[5], acc[r]);
            acc[r] = fmaf(e1.z, w[6], acc[r]);
            acc[r] = fmaf(e1.w, w[7], acc[r]);
        }
    }
    if (ks > 0) {
        #pragma unroll
        for (int r = 0; r < 8; r++) ps[(ks-1)*256 + r*32 + lane] = acc[r];
    }
    __syncthreads();
    if (ks == 0) {
        float bb = B[c];
        #pragma unroll
        for (int r = 0; r < 8; r++) {
            float v = acc[r] + bb;
            #pragma unroll
            for (int u = 0; u < 7; u++) v += ps[u*256 + r*32 + lane];
            if (SILU) v = v / (1.f + expf(-v));
            Out[(r0+r)*outstride + c] = v;
        }
    }
    __syncthreads();
}

// ---------------------------------------------------------------------------
__global__ void __launch_bounds__(256, 2)
mega(const float* __restrict__ noise, const int* __restrict__ ts,
     const float* __restrict__ pcs,   const int* __restrict__ blen,
     const float* __restrict__ pew,   const float* __restrict__ peb,
     const float* __restrict__ tw1,   const float* __restrict__ tb1,
     const float* __restrict__ tw2,   const float* __restrict__ tb2,
     const float* __restrict__ pfw,   const float* __restrict__ pfb,
     const float* __restrict__ ow1,   const float* __restrict__ ob1,
     const float* __restrict__ bn1g,  const float* __restrict__ bn1b,
     const float* __restrict__ ow2,   const float* __restrict__ ob2,
     const float* __restrict__ bn2g,  const float* __restrict__ bn2b,
     const float* __restrict__ ow3,   const float* __restrict__ ob3,
     float* __restrict__ out)
{
    __shared__ float sm[6144];
    __shared__ unsigned sh_epoch;
    int tid = threadIdx.x;
    int lane = tid & 31;
    int warp = tid >> 5;
    int bid = blockIdx.x;

    if (tid == 0) sh_epoch = atomicAdd(&g_tickets, 1u) / NBLK;
    __syncthreads();
    const unsigned e1 = sh_epoch + 1;

    // ===== Aux blocks 224-295: E32, stats zero, W2a, ba; then exit ==========
    // 135 items: [0,4) E32 | 4 stats-zero | [5,133) W2a tiles | [133,135) ba
    if (bid >= 224) {
        for (int item = bid - 224; item < 135; item += 72) {
            if (item < 4) {
                int b2 = item;
                for (int idx = tid; idx < 8*CDIM; idx += 256) {
                    int r = idx >> 9, k = idx & 511;
                    float t = (float)ts[b2*8 + r];
                    int j = k & 255;
                    float f = expf(-9.210340371976184f * (float)j * (1.0f/256.0f));
                    float a = t * f;
                    g_E32[(b2*8 + r)*CDIM + k] = (k < 256) ? cosf(a) : sinf(a);
                }
                signal(C_E32);
            } else if (item == 4) {
                for (int i = tid; i < 768; i += 256) g_stats[i] = 0.f;
                signal(C_E32);
            } else if (item < 133) {
                // W2a tile: tw2 (512x512) @ ow1 (512x256)
                int p = item - 5;
                int rb = p >> 1, cb = p & 1;
                int r0 = rb * 8;
                float* As  = sm;
                float* red = sm + 4096;
                int cl = tid & 127, ks2 = tid >> 7;
                for (int idx = tid; idx < 8*128; idx += 256) {
                    int r = idx >> 7, q = idx & 127;
                    ((float4*)(As + r*CDIM))[q] =
                        ((const float4*)(tw2 + (long)(r0+r)*CDIM))[q];
                }
                __syncthreads();
                float acc[8];
                #pragma unroll
                for (int r = 0; r < 8; r++) acc[r] = 0.f;
                int kbase = ks2 * 256;
                kslice512(As, ow1 + (long)kbase*256 + cb*128 + cl, kbase, acc);
                if (ks2 == 1) {
                    #pragma unroll
                    for (int r = 0; r < 8; r++) red[r*128 + cl] = acc[r];
                }
                __syncthreads();
                if (ks2 == 0) {
                    #pragma unroll
                    for (int r = 0; r < 8; r++)
                        g_W2a[(r0+r)*256 + cb*128 + cl] = acc[r] + red[r*128 + cl];
                }
                __syncthreads();
                signal(C_W2A);
            } else {
                // ba half: tb2 @ ow1 + ob1
                int ci = item - 133;
                if (tid < 128) {
                    int c = ci*128 + tid;
                    float acc = ob1[c];
                    for (int k = 0; k < 512; k += 8) {
                        #pragma unroll
                        for (int u = 0; u < 8; u++)
                            acc = fmaf(tb2[k+u], ow1[(long)(k+u)*256 + c], acc);
                    }
                    g_ba[c] = acc;
                }
                signal(C_W2A);
            }
        }
        return;
    }

    if (bid >= 64) {
        // ===== Y1-side producers: seg prep (warp/seg) or PWa tile ===========
        int item = bid - 64;
        if (item < 80) {
            // 8 segments, one per warp; no block syncs
            int s = item*8 + warp;
            const float* base = pcs + (long)s * (PPP*3);
            float a0 = 0.f, a1 = 0.f, a2 = 0.f;
            for (int j = lane; j < PPP*3; j += 32) {
                float v = base[j];
                int m = j - (j/3)*3;
                if (m == 0) a0 += v; else if (m == 1) a1 += v; else a2 += v;
            }
            #pragma unroll
            for (int o = 16; o; o >>= 1) {
                a0 += __shfl_down_sync(0xffffffffu, a0, o);
                a1 += __shfl_down_sync(0xffffffffu, a1, o);
                a2 += __shfl_down_sync(0xffffffffu, a2, o);
            }
            if (lane == 0) {
                float inv = 1.f / (float)blen[s];
                float px = a0*inv, py = a1*inv, pz = a2*inv;
                float qw = noise[s*7+3], qx = noise[s*7+4];
                float qy = noise[s*7+5], qz = noise[s*7+6];
                float rn = rsqrtf(qw*qw + qx*qx + qy*qy + qz*qz);
                qw*=rn; qx*=rn; qy*=rn; qz*=rn;
                float tx = 2.f*(qy*pz - qz*py);
                float ty = 2.f*(qz*px - qx*pz);
                float tz = 2.f*(qx*py - qy*px);
                g_ctr[s*3+0] = px + qw*tx + (qy*tz - qz*ty) + noise[s*7+0];
                g_ctr[s*3+1] = py + qw*ty + (qz*tx - qx*tz) + noise[s*7+1];
                g_ctr[s*3+2] = pz + qw*tz + (qx*ty - qy*tx) + noise[s*7+2];
            }
            for (int j = lane; j < NERF; j += 32) {
                float v;
                if (j < 7) v = noise[s*7 + j];
                else {
                    int jj = j - 7;
                    int f  = jj / 14;
                    int rr = jj - f*14;
                    float x = noise[s*7 + (rr < 7 ? rr : rr-7)];
                    float arg = x * (float)(1 << f);
                    v = (rr < 7) ? sinf(arg) : cosf(arg);
                }
                g_nerf[s*NERF + j] = v;
            }
        } else if (item < 118) {
            // PWa tile: A = [PFW(147); peb+pfb; PEW(3); 0] (152x512) @ ow1
            int p = item - 80;
            int rb = p >> 1, cb = p & 1;
            int r0 = rb * 8;
            float* As  = sm;
            float* red = sm + 4096;
            int cl = tid & 127, ks2 = tid >> 7;
            for (int idx = tid; idx < 8*CDIM; idx += 256) {
                int r = idx >> 9, k = idx & 511;
                int j = r0 + r;
                float v;
                if (j < 147)       v = pfw[j*CDIM + k];
                else if (j == 147) v = peb[k] + pfb[k];
                else if (j < 151)  v = pew[(j-148)*CDIM + k];
                else               v = 0.f;
                As[idx] = v;
            }
            __syncthreads();
            float acc[8];
            #pragma unroll
            for (int r = 0; r < 8; r++) acc[r] = 0.f;
            int kbase = ks2 * 256;
            kslice512(As, ow1 + (long)kbase*256 + cb*128 + cl, kbase, acc);
            if (ks2 == 1) {
                #pragma unroll
                for (int r = 0; r < 8; r++) red[r*128 + cl] = acc[r];
            }
            __syncthreads();
            if (ks2 == 0) {
                #pragma unroll
                for (int r = 0; r < 8; r++)
                    g_PWa[(r0+r)*256 + cb*128 + cl] = acc[r] + red[r*128 + cl];
            }
            __syncthreads();
        }
        signal(C_A);

        // ===== Y1 tile: [nerf|1|ctr|0] @ PWa (+TB add + bn1 stats) ==========
        wait_ge(C_A, e1*160);
        {
            int t = bid - 64;
            int rb = t >> 1, cb = t & 1;
            int r0 = rb * 8;
            float* En  = sm;
            float* red = sm + 1216;
            int cl = tid & 127, ks2 = tid >> 7;
            int c = cb*128 + cl;
            for (int idx = tid; idx < 8*KAUG; idx += 256) {
                int r = idx / KAUG, j = idx - r*KAUG;
                int s = r0 + r;
                float v;
                if (j < 147)       v = g_nerf[s*NERF + j];
                else if (j == 147) v = 1.f;
                else if (j < 151)  v = g_ctr[s*3 + (j-148)];
                else               v = 0.f;
                En[idx] = v;
            }
            __syncthreads();
            float acc[8];
            #pragma unroll
            for (int r = 0; r < 8; r++) acc[r] = 0.f;
            int kbeg = ks2 ? 80 : 0;
            int kend = ks2 ? KAUG : 80;
            for (int k0 = kbeg; k0 < kend; k0 += 8) {
                float w[8];
                #pragma unroll
                for (int u = 0; u < 8; u++) w[u] = g_PWa[(k0+u)*256 + c];
                #pragma unroll
                for (int r = 0; r < 8; r++) {
                    const float* e = En + r*KAUG + k0;
                    float4 e0 = *(const float4*)e;
                    float4 e1v = *(const float4*)(e+4);
                    acc[r] = fmaf(e0.x, w[0], acc[r]);
                    acc[r] = fmaf(e0.y, w[1], acc[r]);
                    acc[r] = fmaf(e0.z, w[2], acc[r]);
                    acc[r] = fmaf(e0.w, w[3], acc[r]);
                    acc[r] = fmaf(e1v.x, w[4], acc[r]);
                    acc[r] = fmaf(e1v.y, w[5], acc[r]);
                    acc[r] = fmaf(e1v.z, w[6], acc[r]);
                    acc[r] = fmaf(e1v.w, w[7], acc[r]);
                }
            }
            if (ks2 == 1) {
                #pragma unroll
                for (int r = 0; r < 8; r++) red[r*128 + cl] = acc[r];
            }
            __syncthreads();
            wait_ge(C_TB, e1*32);          // overlapped temb chain result
            if (ks2 == 0) {
                float s1 = 0.f, s2 = 0.f;
                #pragma unroll
                for (int r = 0; r < 8; r++) {
                    int s = r0 + r;
                    float y = acc[r] + red[r*128 + cl] + g_TB[(s/20)*256 + c];
                    g_Y1[s*256 + c] = y;
                    s1 += y; s2 += y*y;
                }
                atomicAdd(&g_stats[c], s1);
                atomicAdd(&g_stats[256 + c], s2);
            }
        }
        signal(C_Y1);
        if (bid >= 160) return;
    } else {
        // ===== temb chain on blocks 0-63: th, then TB = th@W2a + ba =========
        wait_ge(C_E32, e1*5);
        mlp_tile<CDIM, true >(sm, tid, lane, bid, g_E32, tw1, tb1, g_th, CDIM);
        signal(C_TH);
        if (bid < 32) {
            wait_ge(C_TH, e1*64);
            wait_ge(C_W2A, e1*130);
            mlp_tile<256, false>(sm, tid, lane, bid, g_th, g_W2a, g_ba, g_TB, 256);
            signal(C_TB);
        }
    }

    // ===== Y2: relu(bn1(Y1)) @ ow2 + ob2; bn2 stats. blocks 0-159 ===========
    wait_ge(C_Y1, e1*160);
    {
        float* scp = sm;            // [256]
        float* sbp = sm + 256;      // [256]
        float* Hs  = sm + 512;      // [4][256]
        float* red = sm + 1536;     // [4][128]
        int cl = tid & 127, ks = tid >> 7;
        int r0 = bid * 4;
        {
            float m = g_stats[tid]       * (1.f/NSEG);
            float v = g_stats[256 + tid] * (1.f/NSEG) - m*m;
            float s = rsqrtf(v + 1e-5f) * bn1g[tid];
            scp[tid] = s; sbp[tid] = bn1b[tid] - m*s;
        }
        __syncthreads();
        for (int idx = tid; idx < 4*256; idx += 256) {
            int r = idx >> 8, j = idx & 255;
            float y = g_Y1[(r0+r)*256 + j];
            Hs[idx] = fmaxf(fmaf(y, scp[j], sbp[j]), 0.f);
        }
        __syncthreads();
        int kbase = ks * 128;
        const float* Wp = ow2 + (long)kbase * 128 + cl;
        float acc[4] = {0.f, 0.f, 0.f, 0.f};
        for (int k0 = 0; k0 < 128; k0 += 8) {
            float w[8];
            #pragma unroll
            for (int u = 0; u < 8; u++) w[u] = Wp[(long)(k0+u)*128];
            #pragma unroll
            for (int r = 0; r < 4; r++) {
                const float* e = Hs + r*256 + kbase + k0;
                float4 e0 = *(const float4*)e;
                float4 e1v = *(const float4*)(e+4);
                acc[r] = fmaf(e0.x, w[0], acc[r]);
                acc[r] = fmaf(e0.y, w[1], acc[r]);
                acc[r] = fmaf(e0.z, w[2], acc[r]);
                acc[r] = fmaf(e0.w, w[3], acc[r]);
                acc[r] = fmaf(e1v.x, w[4], acc[r]);
                acc[r] = fmaf(e1v.y, w[5], acc[r]);
                acc[r] = fmaf(e1v.z, w[6], acc[r]);
                acc[r] = fmaf(e1v.w, w[7], acc[r]);
            }
        }
        if (ks == 1) {
            #pragma unroll
            for (int r = 0; r < 4; r++) red[r*128 + cl] = acc[r];
        }
        __syncthreads();
        if (ks == 0) {
            float bb = ob2[cl];
            float s1 = 0.f, s2 = 0.f;
            #pragma unroll
            for (int r = 0; r < 4; r++) {
                float y = acc[r] + red[r*128 + cl] + bb;
                g_Y2[(r0+r)*128 + cl] = y;
                s1 += y; s2 += y*y;
            }
            atomicAdd(&g_stats[512 + cl], s1);
            atomicAdd(&g_stats[640 + cl], s2);
        }
    }
    signal(C_Y2);

    // ===== out: relu(bn2(Y2)) @ ow3 + ob3. blocks 0-79 ======================
    if (bid < 80) {
        wait_ge(C_Y2, e1*160);
        float* sc = sm;             // [128]
        float* sb = sm + 128;       // [128]
        float* h  = sm + 256;       // [8][128]
        float* w3 = sm + 1280;      // [128*7]
        float* b3 = sm + 2176;      // [7]
        int wid = tid >> 5;
        int r0 = bid * 8;
        if (tid < 128) {
            float m = g_stats[512 + tid] * (1.f/NSEG);
            float v = g_stats[640 + tid] * (1.f/NSEG) - m*m;
            float s = rsqrtf(v + 1e-5f) * bn2g[tid];
            sc[tid] = s; sb[tid] = bn2b[tid] - m*s;
        }
        for (int idx = tid; idx < 128*7; idx += 256) w3[idx] = ow3[idx];
        if (tid < 7) b3[tid] = ob3[tid];
        __syncthreads();
        for (int idx = tid; idx < 8*128; idx += 256) {
            int r = idx >> 7, j = idx & 127;
            float y = g_Y2[(r0+r)*128 + j];
            h[r*128 + j] = fmaxf(fmaf(y, sc[j], sb[j]), 0.f);
        }
        __syncthreads();
        float hv[4];
        #pragma unroll
        for (int u = 0; u < 4; u++) hv[u] = h[wid*128 + lane + u*32];
        #pragma unroll
        for (int j = 0; j < 7; j++) {
            float a = 0.f;
            #pragma unroll
            for (int u = 0; u < 4; u++) a = fmaf(hv[u], w3[(lane + u*32)*7 + j], a);
            #pragma unroll
            for (int o = 16; o; o >>= 1) a += __shfl_down_sync(0xffffffffu, a, o);
            if (lane == 0) out[(r0+wid)*7 + j] = a + b3[j];
        }
    }
}

// ---------------------------------------------------------------------------
extern "C" void kernel_launch(void* const* d_in, const int* in_sizes, int n_in,
                              void* d_out, int out_size)
{
    const float* noise = (const float*)d_in[0];
    const int*   ts    = (const int*)  d_in[1];
    const float* pcs   = (const float*)d_in[2];
    const int*   blen  = (const int*)  d_in[4];
    const float* pew   = (const float*)d_in[5];
    const float* peb   = (const float*)d_in[6];
    const float* tw1   = (const float*)d_in[7];
    const float* tb1   = (const float*)d_in[8];
    const float* tw2   = (const float*)d_in[9];
    const float* tb2   = (const float*)d_in[10];
    const float* pfw   = (const float*)d_in[11];
    const float* pfb   = (const float*)d_in[12];
    const float* ow1   = (const float*)d_in[13];
    const float* ob1   = (const float*)d_in[14];
    const float* bn1g  = (const float*)d_in[15];
    const float* bn1b  = (const float*)d_in[16];
    const float* ow2   = (const float*)d_in[17];
    const float* ob2   = (const float*)d_in[18];
    const float* bn2g  = (const float*)d_in[19];
    const float* bn2b  = (const float*)d_in[20];
    const float* ow3   = (const float*)d_in[21];
    const float* ob3   = (const float*)d_in[22];
    float* out = (float*)d_out;

    mega<<<NBLK, 256>>>(noise, ts, pcs, blen, pew, peb,
                        tw1, tb1, tw2, tb2, pfw, pfb,
                        ow1, ob1, bn1g, bn1b,
                        ow2, ob2, bn2g, bn2b,
                        ow3, ob3, out);
}

// round 17
// speedup vs baseline: 1.2484x; 1.2484x over previous
#include <cuda_runtime.h>
#include <cuda_bf16.h>

// Problem constants
#define CDIM 512
#define NSEG 640         // S
#define PPP  250         // points per segment
#define NB   32          // BO
#define NERF 147         // 7 + 7*10*2
#define NBLK 296         // persistent grid: 2 blocks/SM on 148 SMs
#define KAUG 152         // 147 nerf + 1 bias + 3 ctr + 1 zero pad

// Scratch (__device__ globals; allocation-free rule)
__device__ float g_ctr  [NSEG*3];
__device__ float g_nerf [NSEG*NERF];
__device__ float g_th   [NB*CDIM];    // silu hidden
__device__ float g_temb [NB*CDIM];    // second MLP output
__device__ float g_TB   [NB*256];     // temb @ o_w1 + o_b1
__device__ float g_PWa  [KAUG*256];   // [PFW; peb+pfb; PEW; 0] @ o_w1
__device__ float g_Y1   [NSEG*256];
__device__ float g_Y2   [NSEG*128];
// BN stats: [0,256) sum1 | [256,512) sumsq1 | [512,640) sum2 | [640,768) sumsq2
__device__ float g_stats[768];

// Flag-based sync: monotonic counters (128B apart), epoch via ticket counter.
__device__ unsigned g_tickets;
__device__ unsigned g_c[6*32];
#define C_A    0   // Y1-side producers (seg prep + PWa + stats0)  target/epoch: 160
#define C_TH   1   // th tiles                            64
#define C_TE   2   // temb tiles                          64
#define C_TB   3   // TB tiles                            32
#define C_Y1   4   // Y1 tiles                            160
#define C_Y2   5   // Y2 tiles                            160

__device__ __forceinline__ void wait_ge(int ci, unsigned tgt)
{
    if (threadIdx.x == 0) {
        while (((volatile unsigned*)g_c)[ci*32] < tgt) __nanosleep(40);
        __threadfence();
    }
    __syncthreads();
}
__device__ __forceinline__ void signal(int ci)
{
    __threadfence();
    __syncthreads();
    if (threadIdx.x == 0) atomicAdd(&g_c[ci*32], 1u);
}

// K=256 half-slice FMA: A in smem [8][512], W global row-stride 256.
__device__ __forceinline__ void kslice512(const float* __restrict__ As,
                                          const float* __restrict__ Wp,
                                          int kbase, float acc[8])
{
    for (int k0 = 0; k0 < 256; k0 += 8) {
        float w[8];
        #pragma unroll
        for (int u = 0; u < 8; u++) w[u] = Wp[(long)(k0+u)*256];
        #pragma unroll
        for (int r = 0; r < 8; r++) {
            const float* e = As + r*CDIM + kbase + k0;
            float4 e0 = *(const float4*)e;
            float4 e1 = *(const float4*)(e+4);
            acc[r] = fmaf(e0.x, w[0], acc[r]);
            acc[r] = fmaf(e0.y, w[1], acc[r]);
            acc[r] = fmaf(e0.z, w[2], acc[r]);
            acc[r] = fmaf(e0.w, w[3], acc[r]);
            acc[r] = fmaf(e1.x, w[4], acc[r]);
            acc[r] = fmaf(e1.y, w[5], acc[r]);
            acc[r] = fmaf(e1.z, w[6], acc[r]);
            acc[r] = fmaf(e1.w, w[7], acc[r]);
        }
    }
}

// FMA core for 32-row MLP tile after Es is populated (8r x 32c, 8-way split-K).
template<int WS, bool SILU>
__device__ __forceinline__ void mlp_core(float* sm, int tid, int lane, int t,
                                         const float* __restrict__ W,
                                         const float* __restrict__ B,
                                         float* __restrict__ Out, int outstride)
{
    float* Es = sm;            // [8][512]
    float* ps = sm + 4096;     // [7][8][32]
    int ks = tid >> 5;
    int r0 = (t & 3) * 8;
    int c  = (t >> 2) * 32 + lane;
    int kbase = ks * 64;
    const float* Wp = W + (long)kbase * WS + c;
    float acc[8];
    #pragma unroll
    for (int r = 0; r < 8; r++) acc[r] = 0.f;
    for (int k0 = 0; k0 < 64; k0 += 8) {
        float w[8];
        #pragma unroll
        for (int u = 0; u < 8; u++) w[u] = Wp[(long)(k0+u)*WS];
        #pragma unroll
        for (int r = 0; r < 8; r++) {
            const float* e = Es + r*CDIM + kbase + k0;
            float4 e0 = *(const float4*)e;
            float4 e1 = *(const float4*)(e+4);
            acc[r] = fmaf(e0.x, w[0], acc[r]);
            acc[r] = fmaf(e0.y, w[1], acc[r]);
            acc[r] = fmaf(e0.z, w[2], acc[r]);
            acc[r] = fmaf(e0.w, w[3], acc[r]);
            acc[r] = fmaf(e1.x, w[4], acc[r]);
            acc[r] = fmaf(e1.y, w[5], acc[r]);
            acc[r] = fmaf(e1.z, w[6], acc[r]);
            acc[r] = fmaf(e1.w, w[7], acc[r]);
        }
    }
    if (ks > 0) {
        #pragma unroll
        for (int r = 0; r < 8; r++) ps[(ks-1)*256 + r*32 + lane] = acc[r];
    }
    __syncthreads();
    if (ks == 0) {
        float bb = B[c];
        #pragma unroll
        for (int r = 0; r < 8; r++) {
            float v = acc[r] + bb;
            #pragma unroll
            for (int u = 0; u < 7; u++) v += ps[u*256 + r*32 + lane];
            if (SILU) v = v / (1.f + expf(-v));
            Out[(r0+r)*outstride + c] = v;
        }
    }
    __syncthreads();
}

// Load Es from global (rows r0..r0+7 of Ein, stride CDIM), then run core.
template<int WS, bool SILU>
__device__ __forceinline__ void mlp_tile(float* sm, int tid, int lane, int t,
                                         const float* __restrict__ Ein,
                                         const float* __restrict__ W,
                                         const float* __restrict__ B,
                                         float* __restrict__ Out, int outstride)
{
    float* Es = sm;
    int r0 = (t & 3) * 8;
    for (int idx = tid; idx < 8*128; idx += 256) {
        int r = idx >> 7, q = idx & 127;
        ((float4*)(Es + r*CDIM))[q] = ((const float4*)(Ein + (r0+r)*CDIM))[q];
    }
    __syncthreads();
    mlp_core<WS, SILU>(sm, tid, lane, t, W, B, Out, outstride);
}

// ---------------------------------------------------------------------------
__global__ void __launch_bounds__(256, 2)
mega(const float* __restrict__ noise, const int* __restrict__ ts,
     const float* __restrict__ pcs,   const int* __restrict__ blen,
     const float* __restrict__ pew,   const float* __restrict__ peb,
     const float* __restrict__ tw1,   const float* __restrict__ tb1,
     const float* __restrict__ tw2,   const float* __restrict__ tb2,
     const float* __restrict__ pfw,   const float* __restrict__ pfb,
     const float* __restrict__ ow1,   const float* __restrict__ ob1,
     const float* __restrict__ bn1g,  const float* __restrict__ bn1b,
     const float* __restrict__ ow2,   const float* __restrict__ ob2,
     const float* __restrict__ bn2g,  const float* __restrict__ bn2b,
     const float* __restrict__ ow3,   const float* __restrict__ ob3,
     float* __restrict__ out)
{
    __shared__ float sm[6144];
    __shared__ unsigned sh_epoch;
    int tid = threadIdx.x;
    int lane = tid & 31;
    int warp = tid >> 5;
    int bid = blockIdx.x;

    if (tid == 0) sh_epoch = atomicAdd(&g_tickets, 1u) / NBLK;
    __syncthreads();
    const unsigned e1 = sh_epoch + 1;

    // ===== Aux blocks 224-295: nothing — exit immediately ===================
    if (bid >= 224) return;

    if (bid >= 64) {
        // ===== Y1-side producers: seg prep / PWa tile / stats-zero ==========
        int item = bid - 64;
        if (item < 80) {
            // 8 segments, one per warp; no block syncs
            int s = item*8 + warp;
            const float* base = pcs + (long)s * (PPP*3);
            float a0 = 0.f, a1 = 0.f, a2 = 0.f;
            for (int j = lane; j < PPP*3; j += 32) {
                float v = base[j];
                int m = j - (j/3)*3;
                if (m == 0) a0 += v; else if (m == 1) a1 += v; else a2 += v;
            }
            #pragma unroll
            for (int o = 16; o; o >>= 1) {
                a0 += __shfl_down_sync(0xffffffffu, a0, o);
                a1 += __shfl_down_sync(0xffffffffu, a1, o);
                a2 += __shfl_down_sync(0xffffffffu, a2, o);
            }
            if (lane == 0) {
                float inv = 1.f / (float)blen[s];
                float px = a0*inv, py = a1*inv, pz = a2*inv;
                float qw = noise[s*7+3], qx = noise[s*7+4];
                float qy = noise[s*7+5], qz = noise[s*7+6];
                float rn = rsqrtf(qw*qw + qx*qx + qy*qy + qz*qz);
                qw*=rn; qx*=rn; qy*=rn; qz*=rn;
                float tx = 2.f*(qy*pz - qz*py);
                float ty = 2.f*(qz*px - qx*pz);
                float tz = 2.f*(qx*py - qy*px);
                g_ctr[s*3+0] = px + qw*tx + (qy*tz - qz*ty) + noise[s*7+0];
                g_ctr[s*3+1] = py + qw*ty + (qz*tx - qx*tz) + noise[s*7+1];
                g_ctr[s*3+2] = pz + qw*tz + (qx*ty - qy*tx) + noise[s*7+2];
            }
            for (int j = lane; j < NERF; j += 32) {
                float v;
                if (j < 7) v = noise[s*7 + j];
                else {
                    int jj = j - 7;
                    int f  = jj / 14;
                    int rr = jj - f*14;
                    float x = noise[s*7 + (rr < 7 ? rr : rr-7)];
                    float arg = x * (float)(1 << f);
                    v = (rr < 7) ? sinf(arg) : cosf(arg);
                }
                g_nerf[s*NERF + j] = v;
            }
        } else if (item < 118) {
            // PWa tile: A = [PFW(147); peb+pfb; PEW(3); 0] (152x512) @ ow1
            int p = item - 80;
            int rb = p >> 1, cb = p & 1;
            int r0 = rb * 8;
            float* As  = sm;
            float* red = sm + 4096;
            int cl = tid & 127, ks2 = tid >> 7;
            for (int idx = tid; idx < 8*CDIM; idx += 256) {
                int r = idx >> 9, k = idx & 511;
                int j = r0 + r;
                float v;
                if (j < 147)       v = pfw[j*CDIM + k];
                else if (j == 147) v = peb[k] + pfb[k];
                else if (j < 151)  v = pew[(j-148)*CDIM + k];
                else               v = 0.f;
                As[idx] = v;
            }
            __syncthreads();
            float acc[8];
            #pragma unroll
            for (int r = 0; r < 8; r++) acc[r] = 0.f;
            int kbase = ks2 * 256;
            kslice512(As, ow1 + (long)kbase*256 + cb*128 + cl, kbase, acc);
            if (ks2 == 1) {
                #pragma unroll
                for (int r = 0; r < 8; r++) red[r*128 + cl] = acc[r];
            }
            __syncthreads();
            if (ks2 == 0) {
                #pragma unroll
                for (int r = 0; r < 8; r++)
                    g_PWa[(r0+r)*256 + cb*128 + cl] = acc[r] + red[r*128 + cl];
            }
            __syncthreads();
        } else if (item == 118) {
            // zero BN stats (ordered before all stats atomics via C_A)
            for (int i = tid; i < 768; i += 256) g_stats[i] = 0.f;
        }
        signal(C_A);

        // ===== Y1 tile: [nerf|1|ctr|0] @ PWa (+TB add + bn1 stats) ==========
        wait_ge(C_A, e1*160);
        {
            int t = bid - 64;
            int rb = t >> 1, cb = t & 1;
            int r0 = rb * 8;
            float* En  = sm;
            float* red = sm + 1216;
            int cl = tid & 127, ks2 = tid >> 7;
            int c = cb*128 + cl;
            for (int idx = tid; idx < 8*KAUG; idx += 256) {
                int r = idx / KAUG, j = idx - r*KAUG;
                int s = r0 + r;
                float v;
                if (j < 147)       v = g_nerf[s*NERF + j];
                else if (j == 147) v = 1.f;
                else if (j < 151)  v = g_ctr[s*3 + (j-148)];
                else               v = 0.f;
                En[idx] = v;
            }
            __syncthreads();
            float acc[8];
            #pragma unroll
            for (int r = 0; r < 8; r++) acc[r] = 0.f;
            int kbeg = ks2 ? 80 : 0;
            int kend = ks2 ? KAUG : 80;
            for (int k0 = kbeg; k0 < kend; k0 += 8) {
                float w[8];
                #pragma unroll
                for (int u = 0; u < 8; u++) w[u] = g_PWa[(k0+u)*256 + c];
                #pragma unroll
                for (int r = 0; r < 8; r++) {
                    const float* e = En + r*KAUG + k0;
                    float4 e0 = *(const float4*)e;
                    float4 e1v = *(const float4*)(e+4);
                    acc[r] = fmaf(e0.x, w[0], acc[r]);
                    acc[r] = fmaf(e0.y, w[1], acc[r]);
                    acc[r] = fmaf(e0.z, w[2], acc[r]);
                    acc[r] = fmaf(e0.w, w[3], acc[r]);
                    acc[r] = fmaf(e1v.x, w[4], acc[r]);
                    acc[r] = fmaf(e1v.y, w[5], acc[r]);
                    acc[r] = fmaf(e1v.z, w[6], acc[r]);
                    acc[r] = fmaf(e1v.w, w[7], acc[r]);
                }
            }
            if (ks2 == 1) {
                #pragma unroll
                for (int r = 0; r < 8; r++) red[r*128 + cl] = acc[r];
            }
            __syncthreads();
            wait_ge(C_TB, e1*32);          // overlapped temb chain result
            if (ks2 == 0) {
                float s1 = 0.f, s2 = 0.f;
                #pragma unroll
                for (int r = 0; r < 8; r++) {
                    int s = r0 + r;
                    float y = acc[r] + red[r*128 + cl] + g_TB[(s/20)*256 + c];
                    g_Y1[s*256 + c] = y;
                    s1 += y; s2 += y*y;
                }
                atomicAdd(&g_stats[c], s1);
                atomicAdd(&g_stats[256 + c], s2);
            }
        }
        signal(C_Y1);
        if (bid >= 160) return;
    } else {
        // ===== temb chain on blocks 0-63: E32 computed IN-SMEM (no wait) ====
        {
            float* Es = sm;
            int r0 = (bid & 3) * 8;
            for (int idx = tid; idx < 8*CDIM; idx += 256) {
                int r = idx >> 9, k = idx & 511;
                float t = (float)ts[r0 + r];
                int j = k & 255;
                float f = expf(-9.210340371976184f * (float)j * (1.0f/256.0f));
                float a = t * f;
                Es[r*CDIM + k] = (k < 256) ? cosf(a) : sinf(a);
            }
            __syncthreads();
            mlp_core<CDIM, true>(sm, tid, lane, bid, tw1, tb1, g_th, CDIM);
        }
        signal(C_TH);
        wait_ge(C_TH, e1*64);
        mlp_tile<CDIM, false>(sm, tid, lane, bid, g_th, tw2, tb2, g_temb, CDIM);
        signal(C_TE);
        if (bid < 32) {
            wait_ge(C_TE, e1*64);
            mlp_tile<256, false>(sm, tid, lane, bid, g_temb, ow1, ob1, g_TB, 256);
            signal(C_TB);
        }
    }

    // ===== Y2: relu(bn1(Y1)) @ ow2 + ob2; bn2 stats. blocks 0-159 ===========
    wait_ge(C_Y1, e1*160);
    {
        float* scp = sm;            // [256]
        float* sbp = sm + 256;      // [256]
        float* Hs  = sm + 512;      // [4][256]
        float* red = sm + 1536;     // [4][128]
        int cl = tid & 127, ks = tid >> 7;
        int r0 = bid * 4;
        {
            float m = g_stats[tid]       * (1.f/NSEG);
            float v = g_stats[256 + tid] * (1.f/NSEG) - m*m;
            float s = rsqrtf(v + 1e-5f) * bn1g[tid];
            scp[tid] = s; sbp[tid] = bn1b[tid] - m*s;
        }
        __syncthreads();
        for (int idx = tid; idx < 4*256; idx += 256) {
            int r = idx >> 8, j = idx & 255;
            float y = g_Y1[(r0+r)*256 + j];
            Hs[idx] = fmaxf(fmaf(y, scp[j], sbp[j]), 0.f);
        }
        __syncthreads();
        int kbase = ks * 128;
        const float* Wp = ow2 + (long)kbase * 128 + cl;
        float acc[4] = {0.f, 0.f, 0.f, 0.f};
        for (int k0 = 0; k0 < 128; k0 += 8) {
            float w[8];
            #pragma unroll
            for (int u = 0; u < 8; u++) w[u] = Wp[(long)(k0+u)*128];
            #pragma unroll
            for (int r = 0; r < 4; r++) {
                const float* e = Hs + r*256 + kbase + k0;
                float4 e0 = *(const float4*)e;
                float4 e1v = *(const float4*)(e+4);
                acc[r] = fmaf(e0.x, w[0], acc[r]);
                acc[r] = fmaf(e0.y, w[1], acc[r]);
                acc[r] = fmaf(e0.z, w[2], acc[r]);
                acc[r] = fmaf(e0.w, w[3], acc[r]);
                acc[r] = fmaf(e1v.x, w[4], acc[r]);
                acc[r] = fmaf(e1v.y, w[5], acc[r]);
                acc[r] = fmaf(e1v.z, w[6], acc[r]);
                acc[r] = fmaf(e1v.w, w[7], acc[r]);
            }
        }
        if (ks == 1) {
            #pragma unroll
            for (int r = 0; r < 4; r++) red[r*128 + cl] = acc[r];
        }
        __syncthreads();
        if (ks == 0) {
            float bb = ob2[cl];
            float s1 = 0.f, s2 = 0.f;
            #pragma unroll
            for (int r = 0; r < 4; r++) {
                float y = acc[r] + red[r*128 + cl] + bb;
                g_Y2[(r0+r)*128 + cl] = y;
                s1 += y; s2 += y*y;
            }
            atomicAdd(&g_stats[512 + cl], s1);
            atomicAdd(&g_stats[640 + cl], s2);
        }
    }
    signal(C_Y2);

    // ===== out: relu(bn2(Y2)) @ ow3 + ob3. blocks 0-79 ======================
    if (bid < 80) {
        wait_ge(C_Y2, e1*160);
        float* sc = sm;             // [128]
        float* sb = sm + 128;       // [128]
        float* h  = sm + 256;       // [8][128]
        float* w3 = sm + 1280;      // [128*7]
        float* b3 = sm + 2176;      // [7]
        int wid = tid >> 5;
        int r0 = bid * 8;
        if (tid < 128) {
            float m = g_stats[512 + tid] * (1.f/NSEG);
            float v = g_stats[640 + tid] * (1.f/NSEG) - m*m;
            float s = rsqrtf(v + 1e-5f) * bn2g[tid];
            sc[tid] = s; sb[tid] = bn2b[tid] - m*s;
        }
        for (int idx = tid; idx < 128*7; idx += 256) w3[idx] = ow3[idx];
        if (tid < 7) b3[tid] = ob3[tid];
        __syncthreads();
        for (int idx = tid; idx < 8*128; idx += 256) {
            int r = idx >> 7, j = idx & 127;
            float y = g_Y2[(r0+r)*128 + j];
            h[r*128 + j] = fmaxf(fmaf(y, sc[j], sb[j]), 0.f);
        }
        __syncthreads();
        float hv[4];
        #pragma unroll
        for (int u = 0; u < 4; u++) hv[u] = h[wid*128 + lane + u*32];
        #pragma unroll
        for (int j = 0; j < 7; j++) {
            float a = 0.f;
            #pragma unroll
            for (int u = 0; u < 4; u++) a = fmaf(hv[u], w3[(lane + u*32)*7 + j], a);
            #pragma unroll
            for (int o = 16; o; o >>= 1) a += __shfl_down_sync(0xffffffffu, a, o);
            if (lane == 0) out[(r0+wid)*7 + j] = a + b3[j];
        }
    }
}

// ---------------------------------------------------------------------------
extern "C" void kernel_launch(void* const* d_in, const int* in_sizes, int n_in,
                              void* d_out, int out_size)
{
    const float* noise = (const float*)d_in[0];
    const int*   ts    = (const int*)  d_in[1];
    const float* pcs   = (const float*)d_in[2];
    const int*   blen  = (const int*)  d_in[4];
    const float* pew   = (const float*)d_in[5];
    const float* peb   = (const float*)d_in[6];
    const float* tw1   = (const float*)d_in[7];
    const float* tb1   = (const float*)d_in[8];
    const float* tw2   = (const float*)d_in[9];
    const float* tb2   = (const float*)d_in[10];
    const float* pfw   = (const float*)d_in[11];
    const float* pfb   = (const float*)d_in[12];
    const float* ow1   = (const float*)d_in[13];
    const float* ob1   = (const float*)d_in[14];
    const float* bn1g  = (const float*)d_in[15];
    const float* bn1b  = (const float*)d_in[16];
    const float* ow2   = (const float*)d_in[17];
    const float* ob2   = (const float*)d_in[18];
    const float* bn2g  = (const float*)d_in[19];
    const float* bn2b  = (const float*)d_in[20];
    const float* ow3   = (const float*)d_in[21];
    const float* ob3   = (const float*)d_in[22];
    float* out = (float*)d_out;

    mega<<<NBLK, 256>>>(noise, ts, pcs, blen, pew, peb,
                        tw1, tb1, tw2, tb2, pfw, pfb,
                        ow1, ob1, bn1g, bn1b,
                        ow2, ob2, bn2g, bn2b,
                        ow3, ob3, out);
}